// round 1
// baseline (speedup 1.0000x reference)
#include <cuda_runtime.h>
#include <cstdint>
#include <math.h>

#define NMAX 50000
#define EMAX 600000
#define DD 128
#define NSTEPS 5

// ---------------- device scratch (no allocations allowed) ----------------
__device__ float g_s[4L * NMAX * DD];        // per-type aggregated sums [4][N][128]
__device__ float g_a[(long)NMAX * DD];       // aggregated+transformed   [N][128]
__device__ float g_gi[(long)NMAX * 3 * DD];  // input gates  [N][384]
__device__ float g_gh[(long)NMAX * 3 * DD];  // hidden gates [N][384]
__device__ float g_h[(long)NMAX * DD];       // hidden state ping buffer
__device__ float g_abias[(long)NMAX * DD];   // sum_k cnt[v,k]*b_lin[k]  [N][128]
__device__ int   g_rowptr[NMAX + 1];
__device__ int   g_cnt[NMAX];
__device__ int   g_psrc[EMAX];
__device__ int   g_pet[EMAX];

// ---------------- small helpers ----------------
__device__ __forceinline__ float4 ld4(const float* p) { return *(const float4*)p; }
__device__ __forceinline__ void st4(float* p, float4 v) { *(float4*)p = v; }

__device__ __forceinline__ void cvt2tf32(float x, uint32_t& hi, uint32_t& lo) {
    uint32_t h_;
    asm("cvt.rna.tf32.f32 %0, %1;" : "=r"(h_) : "f"(x));
    float hf = __uint_as_float(h_);
    float r = x - hf;
    uint32_t l_;
    asm("cvt.rna.tf32.f32 %0, %1;" : "=r"(l_) : "f"(r));
    hi = h_; lo = l_;
}

__device__ __forceinline__ void mma_tf32(float d[4], const uint32_t a[4], const uint32_t b[2]) {
    asm volatile(
        "mma.sync.aligned.m16n8k8.row.col.f32.tf32.tf32.f32 "
        "{%0,%1,%2,%3},{%4,%5,%6,%7},{%8,%9},{%0,%1,%2,%3};"
        : "+f"(d[0]), "+f"(d[1]), "+f"(d[2]), "+f"(d[3])
        : "r"(a[0]), "r"(a[1]), "r"(a[2]), "r"(a[3]), "r"(b[0]), "r"(b[1]));
}

// ---------------- CSR build ----------------
__global__ void k_zero_cnt(int N) {
    int i = blockIdx.x * blockDim.x + threadIdx.x;
    if (i < N) g_cnt[i] = 0;
}

__global__ void k_hist(const int* __restrict__ dst, int E) {
    int i = blockIdx.x * blockDim.x + threadIdx.x;
    if (i < E) atomicAdd(&g_cnt[dst[i]], 1);
}

__global__ void k_scan(int N) {
    __shared__ int buf[1024];
    int t = threadIdx.x;
    int C = (N + 1023) >> 10;
    int start = t * C;
    int s = 0;
    for (int i = 0; i < C; i++) {
        int idx = start + i;
        if (idx < N) s += g_cnt[idx];
    }
    buf[t] = s;
    __syncthreads();
    for (int off = 1; off < 1024; off <<= 1) {
        int v = 0;
        if (t >= off) v = buf[t - off];
        __syncthreads();
        buf[t] += v;
        __syncthreads();
    }
    int run = buf[t] - s;
    for (int i = 0; i < C; i++) {
        int idx = start + i;
        if (idx < N) {
            g_rowptr[idx] = run;
            run += g_cnt[idx];
            g_cnt[idx] = 0;  // reset: reused as scatter cursor
        }
    }
    if (t == 1023) g_rowptr[N] = buf[1023];
}

__global__ void k_scatter(const int* __restrict__ src, const int* __restrict__ dst,
                          const int* __restrict__ ety, int E) {
    int i = blockIdx.x * blockDim.x + threadIdx.x;
    if (i < E) {
        int d = dst[i];
        int pos = g_rowptr[d] + atomicAdd(&g_cnt[d], 1);
        g_psrc[pos] = src[i];
        g_pet[pos]  = ety[i] - 1;
    }
}

// abias[v] = sum_k cnt(v,k) * b_lin[k]   (constant across steps)
__global__ void k_abias(const float* __restrict__ b_lin, int N) {
    int warp = (blockIdx.x * blockDim.x + threadIdx.x) >> 5;
    int lane = threadIdx.x & 31;
    if (warp >= N) return;
    int beg = g_rowptr[warp], end = g_rowptr[warp + 1];
    int c0 = 0, c1 = 0, c2 = 0, c3 = 0;
    for (int e = beg; e < end; e++) {
        int k = g_pet[e];
        c0 += (k == 0); c1 += (k == 1); c2 += (k == 2); c3 += (k == 3);
    }
    int c = lane * 4;
    float4 b0 = ld4(b_lin + 0 * DD + c);
    float4 b1 = ld4(b_lin + 1 * DD + c);
    float4 b2 = ld4(b_lin + 2 * DD + c);
    float4 b3 = ld4(b_lin + 3 * DD + c);
    float4 r;
    r.x = c0 * b0.x + c1 * b1.x + c2 * b2.x + c3 * b3.x;
    r.y = c0 * b0.y + c1 * b1.y + c2 * b2.y + c3 * b3.y;
    r.z = c0 * b0.z + c1 * b1.z + c2 * b2.z + c3 * b3.z;
    r.w = c0 * b0.w + c1 * b1.w + c2 * b2.w + c3 * b3.w;
    st4(g_abias + (long)warp * DD + c, r);
}

// ---------------- per-step: edge aggregation (warp per node, CSR) ----------------
__global__ void k_agg(const float* __restrict__ h, int N) {
    int warp = (blockIdx.x * blockDim.x + threadIdx.x) >> 5;
    int lane = threadIdx.x & 31;
    if (warp >= N) return;
    int beg = g_rowptr[warp], end = g_rowptr[warp + 1];
    float4 a0 = make_float4(0, 0, 0, 0), a1 = a0, a2 = a0, a3 = a0;
    int c = lane * 4;
    for (int e = beg; e < end; e++) {
        int sv = g_psrc[e];
        int k  = g_pet[e];
        float4 x = ld4(h + (long)sv * DD + c);
        if (k == 0)      { a0.x += x.x; a0.y += x.y; a0.z += x.z; a0.w += x.w; }
        else if (k == 1) { a1.x += x.x; a1.y += x.y; a1.z += x.z; a1.w += x.w; }
        else if (k == 2) { a2.x += x.x; a2.y += x.y; a2.z += x.z; a2.w += x.w; }
        else             { a3.x += x.x; a3.y += x.y; a3.z += x.z; a3.w += x.w; }
    }
    long base = (long)warp * DD + c;
    long ms = (long)N * DD;
    st4(g_s + 0 * ms + base, a0);
    st4(g_s + 1 * ms + base, a1);
    st4(g_s + 2 * ms + base, a2);
    st4(g_s + 3 * ms + base, a3);
}

// ---------------- tf32 split GEMM:  C[M,ncols] = sum_m A_m[M,128] @ B_m[ncols,128]^T (+bias / +addMat) ----------------
#define SPAD 36

__device__ __forceinline__ void gemm_body(
    const float* __restrict__ A0, long sAmat,
    const float* __restrict__ B0, long sBmat, int nmat,
    const float* __restrict__ biasVec,   // [ncols] or null
    const float* __restrict__ addMat,    // [M][ncols] or null
    float* __restrict__ C, int M, int ncols)
{
    __shared__ float As[128 * SPAD];
    __shared__ float Bs[128 * SPAD];

    int t = threadIdx.x;
    int lane = t & 31;
    int w = t >> 5;
    int wm = w >> 1;      // 0..3 -> 32-row slab
    int wn = w & 1;       // 0..1 -> 64-col slab
    int row0 = blockIdx.x * 128;
    int col0 = blockIdx.y * 128;

    float d[2][8][4];
#pragma unroll
    for (int mi = 0; mi < 2; mi++)
#pragma unroll
        for (int nj = 0; nj < 8; nj++)
#pragma unroll
            for (int q = 0; q < 4; q++) d[mi][nj][q] = 0.f;

    for (int m = 0; m < nmat; m++) {
        const float* A = A0 + (long)m * sAmat;
        const float* B = B0 + (long)m * sBmat;
#pragma unroll
        for (int kc = 0; kc < 128; kc += 32) {
            int r  = t >> 3;
            int c4 = (t & 7) * 4;
#pragma unroll
            for (int i = 0; i < 4; i++) {
                int rr = r + i * 32;
                int gr = row0 + rr;
                float4 x = make_float4(0, 0, 0, 0);
                if (gr < M) x = ld4(A + (long)gr * 128 + kc + c4);
                As[rr * SPAD + c4 + 0] = x.x;
                As[rr * SPAD + c4 + 1] = x.y;
                As[rr * SPAD + c4 + 2] = x.z;
                As[rr * SPAD + c4 + 3] = x.w;
                float4 y = ld4(B + (long)(col0 + rr) * 128 + kc + c4);
                Bs[rr * SPAD + c4 + 0] = y.x;
                Bs[rr * SPAD + c4 + 1] = y.y;
                Bs[rr * SPAD + c4 + 2] = y.z;
                Bs[rr * SPAD + c4 + 3] = y.w;
            }
            __syncthreads();
#pragma unroll
            for (int ks = 0; ks < 4; ks++) {
                int kb = ks * 8 + (lane & 3);
                uint32_t ah[2][4], al[2][4];
#pragma unroll
                for (int mi = 0; mi < 2; mi++) {
                    int mr = wm * 32 + mi * 16 + (lane >> 2);
                    cvt2tf32(As[mr * SPAD + kb],           ah[mi][0], al[mi][0]);
                    cvt2tf32(As[(mr + 8) * SPAD + kb],     ah[mi][1], al[mi][1]);
                    cvt2tf32(As[mr * SPAD + kb + 4],       ah[mi][2], al[mi][2]);
                    cvt2tf32(As[(mr + 8) * SPAD + kb + 4], ah[mi][3], al[mi][3]);
                }
                uint32_t bh[8][2], bl[8][2];
#pragma unroll
                for (int nj = 0; nj < 8; nj++) {
                    int nc = wn * 64 + nj * 8 + (lane >> 2);
                    cvt2tf32(Bs[nc * SPAD + kb],     bh[nj][0], bl[nj][0]);
                    cvt2tf32(Bs[nc * SPAD + kb + 4], bh[nj][1], bl[nj][1]);
                }
#pragma unroll
                for (int mi = 0; mi < 2; mi++)
#pragma unroll
                    for (int nj = 0; nj < 8; nj++) {
                        mma_tf32(d[mi][nj], ah[mi], bh[nj]);
                        mma_tf32(d[mi][nj], al[mi], bh[nj]);
                        mma_tf32(d[mi][nj], ah[mi], bl[nj]);
                    }
            }
            __syncthreads();
        }
    }

    // epilogue
#pragma unroll
    for (int mi = 0; mi < 2; mi++)
#pragma unroll
        for (int nj = 0; nj < 8; nj++) {
            int rb = row0 + wm * 32 + mi * 16 + (lane >> 2);
            int cb = col0 + wn * 64 + nj * 8 + 2 * (lane & 3);
            float b0 = 0.f, b1 = 0.f;
            if (biasVec) { b0 = biasVec[cb]; b1 = biasVec[cb + 1]; }
            if (rb < M) {
                float v0 = d[mi][nj][0] + b0;
                float v1 = d[mi][nj][1] + b1;
                if (addMat) {
                    v0 += addMat[(long)rb * ncols + cb];
                    v1 += addMat[(long)rb * ncols + cb + 1];
                }
                C[(long)rb * ncols + cb]     = v0;
                C[(long)rb * ncols + cb + 1] = v1;
            }
            int rb2 = rb + 8;
            if (rb2 < M) {
                float v2 = d[mi][nj][2] + b0;
                float v3 = d[mi][nj][3] + b1;
                if (addMat) {
                    v2 += addMat[(long)rb2 * ncols + cb];
                    v3 += addMat[(long)rb2 * ncols + cb + 1];
                }
                C[(long)rb2 * ncols + cb]     = v2;
                C[(long)rb2 * ncols + cb + 1] = v3;
            }
        }
}

// a = sum_k s_k @ W_k^T + abias
__global__ void __launch_bounds__(256, 1) k_gemm_a(
    const float* __restrict__ S, const float* __restrict__ W_lin,
    const float* __restrict__ abias, float* __restrict__ Aout, int N)
{
    gemm_body(S, (long)N * 128, W_lin, 128 * 128, 4, nullptr, abias, Aout, N, 128);
}

// z=0: gi = a @ w_ih^T + b_ih ; z=1: gh = h @ w_hh^T + b_hh
__global__ void __launch_bounds__(256, 1) k_gemm_dual(
    const float* __restrict__ A1, const float* __restrict__ B1,
    const float* __restrict__ bias1, float* __restrict__ C1,
    const float* __restrict__ A2, const float* __restrict__ B2,
    const float* __restrict__ bias2, float* __restrict__ C2, int N)
{
    if (blockIdx.z == 0)
        gemm_body(A1, 0, B1, 0, 1, bias1, nullptr, C1, N, 384);
    else
        gemm_body(A2, 0, B2, 0, 1, bias2, nullptr, C2, N, 384);
}

// ---------------- GRU pointwise ----------------
__device__ __forceinline__ float gru1(float ir, float iz, float in_, float hr, float hz, float hn, float hv) {
    float r = 1.f / (1.f + expf(-(ir + hr)));
    float z = 1.f / (1.f + expf(-(iz + hz)));
    float n = tanhf(in_ + r * hn);
    return (1.f - z) * n + z * hv;
}

__global__ void k_gru_pw(const float* __restrict__ gi, const float* __restrict__ gh,
                         const float* __restrict__ h, float* __restrict__ ho, int N) {
    int i = blockIdx.x * blockDim.x + threadIdx.x;
    if (i >= N * 32) return;
    int v = i >> 5;
    int c = (i & 31) * 4;
    const float* giv = gi + (long)v * 384 + c;
    const float* ghv = gh + (long)v * 384 + c;
    float4 ir = ld4(giv), iz = ld4(giv + 128), inn = ld4(giv + 256);
    float4 hr = ld4(ghv), hz = ld4(ghv + 128), hn = ld4(ghv + 256);
    float4 hv = ld4(h + (long)v * DD + c);
    float4 o;
    o.x = gru1(ir.x, iz.x, inn.x, hr.x, hz.x, hn.x, hv.x);
    o.y = gru1(ir.y, iz.y, inn.y, hr.y, hz.y, hn.y, hv.y);
    o.z = gru1(ir.z, iz.z, inn.z, hr.z, hz.z, hn.z, hv.z);
    o.w = gru1(ir.w, iz.w, inn.w, hr.w, hz.w, hn.w, hv.w);
    st4(ho + (long)v * DD + c, o);
}

// ---------------- launch ----------------
extern "C" void kernel_launch(void* const* d_in, const int* in_sizes, int n_in,
                              void* d_out, int out_size) {
    if (n_in < 10) return;
    const float* h_in  = (const float*)d_in[0];
    const int*   src   = (const int*)d_in[1];
    const int*   dst   = (const int*)d_in[2];
    const int*   ety   = (const int*)d_in[3];
    const float* W_lin = (const float*)d_in[4];
    const float* b_lin = (const float*)d_in[5];
    const float* w_ih  = (const float*)d_in[6];
    const float* w_hh  = (const float*)d_in[7];
    const float* b_ih  = (const float*)d_in[8];
    const float* b_hh  = (const float*)d_in[9];

    int N = in_sizes[0] / DD;
    int E = in_sizes[1];
    if (N > NMAX) N = NMAX;
    if (E > EMAX) E = EMAX;

    float *s_p, *a_p, *gi_p, *gh_p, *h_p, *ab_p;
    cudaGetSymbolAddress((void**)&s_p,  g_s);
    cudaGetSymbolAddress((void**)&a_p,  g_a);
    cudaGetSymbolAddress((void**)&gi_p, g_gi);
    cudaGetSymbolAddress((void**)&gh_p, g_gh);
    cudaGetSymbolAddress((void**)&h_p,  g_h);
    cudaGetSymbolAddress((void**)&ab_p, g_abias);

    // CSR build (per launch, identical work every call)
    k_zero_cnt<<<(N + 255) / 256, 256>>>(N);
    k_hist<<<(E + 255) / 256, 256>>>(dst, E);
    k_scan<<<1, 1024>>>(N);
    k_scatter<<<(E + 255) / 256, 256>>>(src, dst, ety, E);
    k_abias<<<(N + 7) / 8, 256>>>(b_lin, N);

    int gx = (N + 127) / 128;
    const float* hcur = h_in;
    for (int s = 0; s < NSTEPS; s++) {
        float* hout = (s == NSTEPS - 1) ? (float*)d_out : h_p;
        k_agg<<<(N + 7) / 8, 256>>>(hcur, N);
        k_gemm_a<<<dim3(gx, 1), 256>>>(s_p, W_lin, ab_p, a_p, N);
        k_gemm_dual<<<dim3(gx, 3, 2), 256>>>(a_p, w_ih, b_ih, gi_p,
                                             hcur, w_hh, b_hh, gh_p, N);
        k_gru_pw<<<(N * 32 + 255) / 256, 256>>>(gi_p, gh_p, hcur, hout, N);
        hcur = hout;
    }
}

// round 3
// speedup vs baseline: 1.3012x; 1.3012x over previous
#include <cuda_runtime.h>
#include <cuda_bf16.h>
#include <cstdint>
#include <math.h>

#define NMAX 50000
#define EMAX 600000
#define DD 128
#define NSTEPS 5

// weight pre-split layout (bf16 hi/lo): [W_lin 4*128*128 | w_ih 384*128 | w_hh 384*128]
#define OFF_WLIN 0
#define OFF_WIH  65536
#define OFF_WHH  114688
#define W_TOT    163840

// ---------------- device scratch (no allocations allowed) ----------------
__device__ __align__(16) float g_s[4L * NMAX * DD];
__device__ __align__(16) float g_a[(long)NMAX * DD];
__device__ __align__(16) float g_gi[(long)NMAX * 3 * DD];
__device__ __align__(16) float g_gh[(long)NMAX * 3 * DD];
__device__ __align__(16) float g_h[(long)NMAX * DD];
__device__ __align__(16) float g_abias[(long)NMAX * DD];
__device__ __align__(16) __nv_bfloat16 g_wh[W_TOT];
__device__ __align__(16) __nv_bfloat16 g_wl[W_TOT];
__device__ int g_rowptr[NMAX + 1];
__device__ int g_cnt[NMAX];
__device__ int g_psrc[EMAX];
__device__ int g_pet[EMAX];

// ---------------- helpers ----------------
__device__ __forceinline__ float4 ld4(const float* p) { return *(const float4*)p; }
__device__ __forceinline__ void st4(float* p, float4 v) { *(float4*)p = v; }

// pack two floats -> bf16x2 (lo -> low half, hi -> high half)
__device__ __forceinline__ uint32_t packbf(float lo, float hi) {
    uint32_t r;
    asm("cvt.rn.bf16x2.f32 %0, %1, %2;" : "=r"(r) : "f"(hi), "f"(lo));
    return r;
}
__device__ __forceinline__ float f_lo(uint32_t p) { return __uint_as_float(p << 16); }
__device__ __forceinline__ float f_hi(uint32_t p) { return __uint_as_float(p & 0xffff0000u); }

__device__ __forceinline__ void mma_bf16(float* d, const uint32_t* a, uint32_t b0, uint32_t b1) {
    asm volatile(
        "mma.sync.aligned.m16n8k16.row.col.f32.bf16.bf16.f32 "
        "{%0,%1,%2,%3},{%4,%5,%6,%7},{%8,%9},{%0,%1,%2,%3};"
        : "+f"(d[0]), "+f"(d[1]), "+f"(d[2]), "+f"(d[3])
        : "r"(a[0]), "r"(a[1]), "r"(a[2]), "r"(a[3]), "r"(b0), "r"(b1));
}

__device__ __forceinline__ float tanh_fast(float x) {
    float r;
    asm("tanh.approx.f32 %0, %1;" : "=f"(r) : "f"(x));
    return r;
}

// ---------------- weight pre-split ----------------
__global__ void k_split_w(const float* __restrict__ Wlin, const float* __restrict__ wih,
                          const float* __restrict__ whh) {
    int i = blockIdx.x * blockDim.x + threadIdx.x;
    if (i >= W_TOT) return;
    float x;
    if (i < OFF_WIH) x = Wlin[i];
    else if (i < OFF_WHH) x = wih[i - OFF_WIH];
    else x = whh[i - OFF_WHH];
    __nv_bfloat16 h = __float2bfloat16(x);
    g_wh[i] = h;
    g_wl[i] = __float2bfloat16(x - __bfloat162float(h));
}

// ---------------- CSR build ----------------
__global__ void k_zero_cnt(int N) {
    int i = blockIdx.x * blockDim.x + threadIdx.x;
    if (i < N) g_cnt[i] = 0;
}

__global__ void k_hist(const int* __restrict__ dst, int E) {
    int i = blockIdx.x * blockDim.x + threadIdx.x;
    if (i < E) atomicAdd(&g_cnt[dst[i]], 1);
}

__global__ void k_scan(int N) {
    __shared__ int buf[1024];
    int t = threadIdx.x;
    int C = (N + 1023) >> 10;
    int start = t * C;
    int s = 0;
    for (int i = 0; i < C; i++) {
        int idx = start + i;
        if (idx < N) s += g_cnt[idx];
    }
    buf[t] = s;
    __syncthreads();
    for (int off = 1; off < 1024; off <<= 1) {
        int v = 0;
        if (t >= off) v = buf[t - off];
        __syncthreads();
        buf[t] += v;
        __syncthreads();
    }
    int run = buf[t] - s;
    for (int i = 0; i < C; i++) {
        int idx = start + i;
        if (idx < N) {
            g_rowptr[idx] = run;
            run += g_cnt[idx];
            g_cnt[idx] = 0;
        }
    }
    if (t == 1023) g_rowptr[N] = buf[1023];
}

__global__ void k_scatter(const int* __restrict__ src, const int* __restrict__ dst,
                          const int* __restrict__ ety, int E) {
    int i = blockIdx.x * blockDim.x + threadIdx.x;
    if (i < E) {
        int d = dst[i];
        int pos = g_rowptr[d] + atomicAdd(&g_cnt[d], 1);
        g_psrc[pos] = src[i];
        g_pet[pos]  = ety[i] - 1;
    }
}

__global__ void k_abias(const float* __restrict__ b_lin, int N) {
    int warp = (blockIdx.x * blockDim.x + threadIdx.x) >> 5;
    int lane = threadIdx.x & 31;
    if (warp >= N) return;
    int beg = g_rowptr[warp], end = g_rowptr[warp + 1];
    int c0 = 0, c1 = 0, c2 = 0, c3 = 0;
    for (int e = beg; e < end; e++) {
        int k = g_pet[e];
        c0 += (k == 0); c1 += (k == 1); c2 += (k == 2); c3 += (k == 3);
    }
    int c = lane * 4;
    float4 b0 = ld4(b_lin + 0 * DD + c);
    float4 b1 = ld4(b_lin + 1 * DD + c);
    float4 b2 = ld4(b_lin + 2 * DD + c);
    float4 b3 = ld4(b_lin + 3 * DD + c);
    float4 r;
    r.x = c0 * b0.x + c1 * b1.x + c2 * b2.x + c3 * b3.x;
    r.y = c0 * b0.y + c1 * b1.y + c2 * b2.y + c3 * b3.y;
    r.z = c0 * b0.z + c1 * b1.z + c2 * b2.z + c3 * b3.z;
    r.w = c0 * b0.w + c1 * b1.w + c2 * b2.w + c3 * b3.w;
    st4(g_abias + (long)warp * DD + c, r);
}

// ---------------- per-step: edge aggregation (warp per node, CSR) ----------------
__global__ void k_agg(const float* __restrict__ h, int N) {
    int warp = (blockIdx.x * blockDim.x + threadIdx.x) >> 5;
    int lane = threadIdx.x & 31;
    if (warp >= N) return;
    int beg = g_rowptr[warp], end = g_rowptr[warp + 1];
    float4 a0 = make_float4(0, 0, 0, 0), a1 = a0, a2 = a0, a3 = a0;
    int c = lane * 4;
    for (int e = beg; e < end; e++) {
        int sv = g_psrc[e];
        int k  = g_pet[e];
        float4 x = ld4(h + (long)sv * DD + c);
        if (k == 0)      { a0.x += x.x; a0.y += x.y; a0.z += x.z; a0.w += x.w; }
        else if (k == 1) { a1.x += x.x; a1.y += x.y; a1.z += x.z; a1.w += x.w; }
        else if (k == 2) { a2.x += x.x; a2.y += x.y; a2.z += x.z; a2.w += x.w; }
        else             { a3.x += x.x; a3.y += x.y; a3.z += x.z; a3.w += x.w; }
    }
    long base = (long)warp * DD + c;
    long ms = (long)N * DD;
    st4(g_s + 0 * ms + base, a0);
    st4(g_s + 1 * ms + base, a1);
    st4(g_s + 2 * ms + base, a2);
    st4(g_s + 3 * ms + base, a3);
}

// ---------------- bf16 3-term split GEMM ----------------
// C[M,ncols] = sum_m A_m[M,128] @ Bsplit_m[ncols,128]^T (+bias / +addMat)
// A fp32 global; B pre-split bf16 hi/lo in g_wh/g_wl at boff (+ m*sBmat).
#define RS 20  // smem row stride in u32 (16 data + 4 pad -> conflict-free frag loads)

__device__ __forceinline__ void gemm_body(
    const float* __restrict__ A0, long sAmat,
    long boff, long sBmat, int nmat,
    const float* __restrict__ biasVec,
    const float* __restrict__ addMat,
    float* __restrict__ C, int M, int ncols)
{
    __shared__ __align__(16) uint32_t As_h[128 * RS];
    __shared__ __align__(16) uint32_t As_l[128 * RS];
    __shared__ __align__(16) uint32_t Bs_h[128 * RS];
    __shared__ __align__(16) uint32_t Bs_l[128 * RS];

    int t = threadIdx.x;
    int lane = t & 31;
    int w = t >> 5;
    int wm = w >> 1;      // 0..3 -> 32-row slab
    int wn = w & 1;       // 0..1 -> 64-col slab
    int row0 = blockIdx.x * 128;
    int col0 = blockIdx.y * 128;
    int g   = lane >> 2;
    int tig = lane & 3;

    float d[2][8][4];
#pragma unroll
    for (int mi = 0; mi < 2; mi++)
#pragma unroll
        for (int nj = 0; nj < 8; nj++)
#pragma unroll
            for (int q = 0; q < 4; q++) d[mi][nj][q] = 0.f;

    for (int m = 0; m < nmat; m++) {
        const float* A = A0 + (long)m * sAmat;
        long bbase = boff + (long)m * sBmat;
#pragma unroll
        for (int kc = 0; kc < 128; kc += 32) {
            // stage A: fp32 -> split bf16x2 pairs
            {
                int r  = t >> 3;
                int c4 = (t & 7) * 4;
#pragma unroll
                for (int i = 0; i < 4; i++) {
                    int rr = r + i * 32;
                    int gr = row0 + rr;
                    float4 x = make_float4(0, 0, 0, 0);
                    if (gr < M) x = ld4(A + (long)gr * 128 + kc + c4);
                    uint32_t h0 = packbf(x.x, x.y);
                    uint32_t h1 = packbf(x.z, x.w);
                    uint32_t l0 = packbf(x.x - f_lo(h0), x.y - f_hi(h0));
                    uint32_t l1 = packbf(x.z - f_lo(h1), x.w - f_hi(h1));
                    int si = rr * RS + (c4 >> 1);
                    *(uint2*)&As_h[si] = make_uint2(h0, h1);
                    *(uint2*)&As_l[si] = make_uint2(l0, l1);
                }
            }
            // stage B: pre-split bf16 from global
            {
                int col  = t >> 1;
                int half = t & 1;
                long gi_ = bbase + (long)(col0 + col) * 128 + kc + half * 16;
                const uint4* ph = (const uint4*)(g_wh + gi_);
                const uint4* pl = (const uint4*)(g_wl + gi_);
                uint4 vh0 = ph[0], vh1 = ph[1];
                uint4 vl0 = pl[0], vl1 = pl[1];
                int si = col * RS + half * 8;
                *(uint4*)&Bs_h[si]     = vh0;
                *(uint4*)&Bs_h[si + 4] = vh1;
                *(uint4*)&Bs_l[si]     = vl0;
                *(uint4*)&Bs_l[si + 4] = vl1;
            }
            __syncthreads();
#pragma unroll
            for (int ks = 0; ks < 2; ks++) {
                int kb = ks * 8;
                uint32_t ah[2][4], al[2][4];
#pragma unroll
                for (int mi = 0; mi < 2; mi++) {
                    int rbase = (wm * 32 + mi * 16 + g) * RS + kb + tig;
                    ah[mi][0] = As_h[rbase];
                    ah[mi][1] = As_h[rbase + 8 * RS];
                    ah[mi][2] = As_h[rbase + 4];
                    ah[mi][3] = As_h[rbase + 8 * RS + 4];
                    al[mi][0] = As_l[rbase];
                    al[mi][1] = As_l[rbase + 8 * RS];
                    al[mi][2] = As_l[rbase + 4];
                    al[mi][3] = As_l[rbase + 8 * RS + 4];
                }
#pragma unroll
                for (int nj = 0; nj < 8; nj++) {
                    int cb = (wn * 64 + nj * 8 + g) * RS + kb + tig;
                    uint32_t bh0 = Bs_h[cb], bh1 = Bs_h[cb + 4];
                    uint32_t bl0 = Bs_l[cb], bl1 = Bs_l[cb + 4];
#pragma unroll
                    for (int mi = 0; mi < 2; mi++) {
                        mma_bf16(d[mi][nj], ah[mi], bh0, bh1);
                        mma_bf16(d[mi][nj], al[mi], bh0, bh1);
                        mma_bf16(d[mi][nj], ah[mi], bl0, bl1);
                    }
                }
            }
            __syncthreads();
        }
    }

    // epilogue
#pragma unroll
    for (int mi = 0; mi < 2; mi++)
#pragma unroll
        for (int nj = 0; nj < 8; nj++) {
            int rb = row0 + wm * 32 + mi * 16 + g;
            int cb = col0 + wn * 64 + nj * 8 + 2 * tig;
            float b0 = 0.f, b1 = 0.f;
            if (biasVec) { b0 = biasVec[cb]; b1 = biasVec[cb + 1]; }
            if (rb < M) {
                float v0 = d[mi][nj][0] + b0;
                float v1 = d[mi][nj][1] + b1;
                if (addMat) {
                    v0 += addMat[(long)rb * ncols + cb];
                    v1 += addMat[(long)rb * ncols + cb + 1];
                }
                C[(long)rb * ncols + cb]     = v0;
                C[(long)rb * ncols + cb + 1] = v1;
            }
            int rb2 = rb + 8;
            if (rb2 < M) {
                float v2 = d[mi][nj][2] + b0;
                float v3 = d[mi][nj][3] + b1;
                if (addMat) {
                    v2 += addMat[(long)rb2 * ncols + cb];
                    v3 += addMat[(long)rb2 * ncols + cb + 1];
                }
                C[(long)rb2 * ncols + cb]     = v2;
                C[(long)rb2 * ncols + cb + 1] = v3;
            }
        }
}

// a = sum_k s_k @ W_k^T + abias
__global__ void __launch_bounds__(256, 2) k_gemm_a(
    const float* __restrict__ S, const float* __restrict__ abias,
    float* __restrict__ Aout, int N)
{
    gemm_body(S, (long)N * 128, OFF_WLIN, 128 * 128, 4, nullptr, abias, Aout, N, 128);
}

// z=0: gi = a @ w_ih^T + b_ih ; z=1: gh = h @ w_hh^T + b_hh
__global__ void __launch_bounds__(256, 2) k_gemm_dual(
    const float* __restrict__ A1, const float* __restrict__ bias1, float* __restrict__ C1,
    const float* __restrict__ A2, const float* __restrict__ bias2, float* __restrict__ C2,
    int N)
{
    if (blockIdx.z == 0)
        gemm_body(A1, 0, OFF_WIH, 0, 1, bias1, nullptr, C1, N, 384);
    else
        gemm_body(A2, 0, OFF_WHH, 0, 1, bias2, nullptr, C2, N, 384);
}

// ---------------- GRU pointwise ----------------
__device__ __forceinline__ float gru1(float ir, float iz, float in_, float hr, float hz, float hn, float hv) {
    float r = 1.f / (1.f + __expf(-(ir + hr)));
    float z = 1.f / (1.f + __expf(-(iz + hz)));
    float n = tanh_fast(in_ + r * hn);
    return (1.f - z) * n + z * hv;
}

__global__ void k_gru_pw(const float* __restrict__ gi, const float* __restrict__ gh,
                         const float* __restrict__ h, float* __restrict__ ho, int N) {
    int i = blockIdx.x * blockDim.x + threadIdx.x;
    if (i >= N * 32) return;
    int v = i >> 5;
    int c = (i & 31) * 4;
    const float* giv = gi + (long)v * 384 + c;
    const float* ghv = gh + (long)v * 384 + c;
    float4 ir = ld4(giv), iz = ld4(giv + 128), inn = ld4(giv + 256);
    float4 hr = ld4(ghv), hz = ld4(ghv + 128), hn = ld4(ghv + 256);
    float4 hv = ld4(h + (long)v * DD + c);
    float4 o;
    o.x = gru1(ir.x, iz.x, inn.x, hr.x, hz.x, hn.x, hv.x);
    o.y = gru1(ir.y, iz.y, inn.y, hr.y, hz.y, hn.y, hv.y);
    o.z = gru1(ir.z, iz.z, inn.z, hr.z, hz.z, hn.z, hv.z);
    o.w = gru1(ir.w, iz.w, inn.w, hr.w, hz.w, hn.w, hv.w);
    st4(ho + (long)v * DD + c, o);
}

// ---------------- launch ----------------
extern "C" void kernel_launch(void* const* d_in, const int* in_sizes, int n_in,
                              void* d_out, int out_size) {
    if (n_in < 10) return;
    const float* h_in  = (const float*)d_in[0];
    const int*   src   = (const int*)d_in[1];
    const int*   dst   = (const int*)d_in[2];
    const int*   ety   = (const int*)d_in[3];
    const float* W_lin = (const float*)d_in[4];
    const float* b_lin = (const float*)d_in[5];
    const float* w_ih  = (const float*)d_in[6];
    const float* w_hh  = (const float*)d_in[7];
    const float* b_ih  = (const float*)d_in[8];
    const float* b_hh  = (const float*)d_in[9];

    int N = in_sizes[0] / DD;
    int E = in_sizes[1];
    if (N > NMAX) N = NMAX;
    if (E > EMAX) E = EMAX;

    float *s_p, *a_p, *gi_p, *gh_p, *h_p, *ab_p;
    cudaGetSymbolAddress((void**)&s_p,  g_s);
    cudaGetSymbolAddress((void**)&a_p,  g_a);
    cudaGetSymbolAddress((void**)&gi_p, g_gi);
    cudaGetSymbolAddress((void**)&gh_p, g_gh);
    cudaGetSymbolAddress((void**)&h_p,  g_h);
    cudaGetSymbolAddress((void**)&ab_p, g_abias);

    // one-time prep (runs each replay; cheap)
    k_split_w<<<(W_TOT + 255) / 256, 256>>>(W_lin, w_ih, w_hh);
    k_zero_cnt<<<(N + 255) / 256, 256>>>(N);
    k_hist<<<(E + 255) / 256, 256>>>(dst, E);
    k_scan<<<1, 1024>>>(N);
    k_scatter<<<(E + 255) / 256, 256>>>(src, dst, ety, E);
    k_abias<<<(N + 7) / 8, 256>>>(b_lin, N);

    int gx = (N + 127) / 128;
    const float* hcur = h_in;
    for (int s = 0; s < NSTEPS; s++) {
        float* hout = (s == NSTEPS - 1) ? (float*)d_out : h_p;
        k_agg<<<(N + 7) / 8, 256>>>(hcur, N);
        k_gemm_a<<<dim3(gx, 1), 256>>>(s_p, ab_p, a_p, N);
        k_gemm_dual<<<dim3(gx, 3, 2), 256>>>(a_p, b_ih, gi_p, hcur, b_hh, gh_p, N);
        k_gru_pw<<<(N * 32 + 255) / 256, 256>>>(gi_p, gh_p, hcur, hout, N);
        hcur = hout;
    }
}